// round 1
// baseline (speedup 1.0000x reference)
#include <cuda_runtime.h>
#include <cuda_bf16.h>
#include <math.h>

// ---------------- problem constants ----------------
#define BB   4
#define CC   192
#define HH   64
#define WW   64
#define LL   (HH*WW)          // 4096
#define MM   (BB*LL)          // 16384
#define DI   384
#define DS   16
#define DTR  12
#define NDBL 44               // DTR + 2*DS
#define DC   4
#define NC   32               // scan chunks
#define LC   (LL/NC)          // 128
#define LOG2E 1.4426950408889634f

// ---------------- scratch (device globals: allocation-free) ----------------
__device__ float g_xn [MM*CC];          // layernormed input, (m, c)
__device__ float g_xz [(size_t)MM*768]; // in_proj output: cols [0,384)=xi, [384,768)=z
__device__ float g_xs [2][(size_t)MM*DI];  // conv+silu per direction, (m, d)
__device__ float g_dbl[2][(size_t)MM*NDBL];// x_proj output, (m, 44)
__device__ float g_dt [2][(size_t)MM*DI];  // softplus(dt), (m, d)
__device__ float g_y  [2][(size_t)MM*DI];  // scan output, (m, d)
__device__ float g_G  [(size_t)MM*DI];     // fused gate for out_proj
__device__ float g_hend  [2*BB*NC*DI*DS];
__device__ float g_pend  [2*BB*NC*DI*DS];
__device__ float g_hstart[2*BB*NC*DI*DS];

__device__ __forceinline__ float ex2(float x){
    float r; asm("ex2.approx.ftz.f32 %0, %1;" : "=f"(r) : "f"(x)); return r;
}
__device__ __forceinline__ float silu_f(float x){
    return x / (1.f + __expf(-x));
}

// ---------------- 1) LayerNorm over channels ----------------
// x: (B, C, L) -> g_xn: (m, c)   grid(L/32, B), block(32,8)
__global__ void ln_kernel(const float* __restrict__ x,
                          const float* __restrict__ w,
                          const float* __restrict__ bsh)
{
    int b = blockIdx.y, p0 = blockIdx.x * 32;
    int tx = threadIdx.x, ty = threadIdx.y;
    __shared__ float sx[CC][33];
    __shared__ float red[2][8][32];
    __shared__ float smu[32], srs[32];

    float s1 = 0.f, s2 = 0.f;
    for (int c = ty; c < CC; c += 8) {
        float v = x[((size_t)(b*CC + c))*LL + p0 + tx];
        sx[c][tx] = v; s1 += v; s2 += v*v;
    }
    red[0][ty][tx] = s1; red[1][ty][tx] = s2;
    __syncthreads();
    if (ty == 0) {
        float a = 0.f, q = 0.f;
        #pragma unroll
        for (int j = 0; j < 8; j++){ a += red[0][j][tx]; q += red[1][j][tx]; }
        float mu = a / CC;
        float var = q / CC - mu*mu;
        smu[tx] = mu; srs[tx] = rsqrtf(var + 1e-5f);
    }
    __syncthreads();
    int tid = ty*32 + tx;
    for (int e = tid; e < 32*CC; e += 256) {
        int pp = e / CC, cc = e % CC;
        float v = (sx[cc][pp] - smu[pp]) * srs[pp] * w[cc] + bsh[cc];
        g_xn[((size_t)(b*LL + p0 + pp))*CC + cc] = v;
    }
}

// ---------------- generic SIMT GEMM, C[m,n] = sum_k A[m,k]*Bw[n,k] ----------------
// MODE 0: plain store. MODE 1: +bias, softplus. MODE 2: transpose-write to (B,C,L) output.
template<int MODE>
__global__ void gemm_nt(const float* __restrict__ A, const float* __restrict__ Bw,
                        float* __restrict__ Cout,
                        int lda, int ldb, int ldc, int N, int K,
                        const float* __restrict__ bias, float* __restrict__ dout)
{
    const int BM = 64, BN = 64, BK = 16;
    __shared__ __align__(16) float As[BK][BM];
    __shared__ __align__(16) float Bs[BK][BN];
    __shared__ float strans[(MODE == 2) ? 64*65 : 1];

    int tid = threadIdx.x;
    int m0 = blockIdx.y * BM, n0 = blockIdx.x * BN;
    int ty = tid / 16, tx = tid % 16;

    float acc[4][4];
    #pragma unroll
    for (int i = 0; i < 4; i++)
        #pragma unroll
        for (int j = 0; j < 4; j++) acc[i][j] = 0.f;

    for (int k0 = 0; k0 < K; k0 += BK) {
        #pragma unroll
        for (int e = 0; e < 4; e++) {
            int idx = tid + e*256;
            int mm = idx / BK, kk = idx % BK;
            float v = 0.f;
            if (k0 + kk < K) v = A[(size_t)(m0 + mm)*lda + k0 + kk];
            As[kk][mm] = v;
        }
        #pragma unroll
        for (int e = 0; e < 4; e++) {
            int idx = tid + e*256;
            int nn = idx / BK, kk = idx % BK;
            float v = 0.f;
            if ((n0 + nn) < N && (k0 + kk) < K) v = Bw[(size_t)(n0 + nn)*ldb + k0 + kk];
            Bs[kk][nn] = v;
        }
        __syncthreads();
        #pragma unroll
        for (int k = 0; k < BK; k++) {
            float4 av = *(const float4*)&As[k][ty*4];
            float4 bv = *(const float4*)&Bs[k][tx*4];
            float a[4] = {av.x, av.y, av.z, av.w};
            float b[4] = {bv.x, bv.y, bv.z, bv.w};
            #pragma unroll
            for (int i = 0; i < 4; i++)
                #pragma unroll
                for (int j = 0; j < 4; j++)
                    acc[i][j] = fmaf(a[i], b[j], acc[i][j]);
        }
        __syncthreads();
    }

    if (MODE == 0 || MODE == 1) {
        #pragma unroll
        for (int i = 0; i < 4; i++) {
            int m = m0 + ty*4 + i;
            #pragma unroll
            for (int j = 0; j < 4; j++) {
                int n = n0 + tx*4 + j;
                if (n < N) {
                    float v = acc[i][j];
                    if (MODE == 1) {
                        v += bias[n];
                        v = (v > 20.f) ? v : log1pf(expf(v));
                    }
                    Cout[(size_t)m*ldc + n] = v;
                }
            }
        }
    } else { // MODE 2: write d_out[(b*C + n)*L + p], m = b*L + p
        #pragma unroll
        for (int i = 0; i < 4; i++)
            #pragma unroll
            for (int j = 0; j < 4; j++)
                strans[(tx*4 + j)*65 + (ty*4 + i)] = acc[i][j];
        __syncthreads();
        for (int e = tid; e < 64*64; e += 256) {
            int nn = e >> 6, mm = e & 63;
            int m = m0 + mm;
            int b = m >> 12, p = m & (LL - 1);
            int n = n0 + nn;
            if (n < N)
                dout[((size_t)(b*CC + n))*LL + p] = strans[nn*65 + mm];
        }
    }
}

// ---------------- 3) depthwise causal conv (both directions) + silu ----------------
// grid (L/16, B), block 384
__global__ void conv_silu_kernel(const float* __restrict__ cw, const float* __restrict__ cb)
{
    __shared__ float s[16 + 6][DI];
    int b = blockIdx.y, t0 = blockIdx.x * 16, d = threadIdx.x;

    #pragma unroll
    for (int j = 0; j < 22; j++) {
        int t = t0 - 3 + j;
        float v = 0.f;
        if (t >= 0 && t < LL) v = g_xz[((size_t)(b*LL + t))*768 + d];
        s[j][d] = v;
    }
    __syncthreads();
    float w0 = cw[d*4+0], w1 = cw[d*4+1], w2 = cw[d*4+2], w3 = cw[d*4+3];
    float bias = cb[d];
    #pragma unroll
    for (int tt = 0; tt < 16; tt++) {
        // forward causal: sum_k w[k]*xi[t-3+k]
        float of = w0*s[tt][d] + w1*s[tt+1][d] + w2*s[tt+2][d] + w3*s[tt+3][d] + bias;
        // backward (flip-conv-flip): sum_j w[3-j]*xi[t+j]
        float ob = w3*s[tt+3][d] + w2*s[tt+4][d] + w1*s[tt+5][d] + w0*s[tt+6][d] + bias;
        size_t m = (size_t)(b*LL + t0 + tt);
        g_xs[0][m*DI + d] = silu_f(of);
        g_xs[1][m*DI + d] = silu_f(ob);
    }
}

// ---------------- scan pass 1: per-chunk local scan -> (h_end, P_end) ----------------
// grid(DI/128, NC, 2*B), block 128
__global__ void scan_pass1(const float* __restrict__ A_log)
{
    int d  = blockIdx.x * 128 + threadIdx.x;
    int c  = blockIdx.y;
    int rb = blockIdx.z;
    int r  = rb >> 2, b = rb & 3;

    float A2[DS], h[DS];
    #pragma unroll
    for (int sIdx = 0; sIdx < DS; sIdx++) {
        A2[sIdx] = -__expf(A_log[d*DS + sIdx]) * LOG2E;
        h[sIdx]  = 0.f;
    }
    const float* dtp  = g_dt[r];
    const float* up   = g_xs[r];
    const float* dblp = g_dbl[r];
    float S = 0.f;

    for (int t = 0; t < LC; t++) {
        int tau = c*LC + t;
        int pos = r ? (LL - 1 - tau) : tau;
        size_t m = (size_t)b*LL + pos;
        float dt  = dtp[m*DI + d];
        float u   = up [m*DI + d];
        float dtx = dt * u;
        const float4* Bv = (const float4*)(dblp + m*NDBL + DTR);
        float4 b0 = Bv[0], b1 = Bv[1], b2 = Bv[2], b3 = Bv[3];
        float Bvals[DS] = {b0.x,b0.y,b0.z,b0.w, b1.x,b1.y,b1.z,b1.w,
                           b2.x,b2.y,b2.z,b2.w, b3.x,b3.y,b3.z,b3.w};
        #pragma unroll
        for (int sIdx = 0; sIdx < DS; sIdx++) {
            float a = ex2(dt * A2[sIdx]);
            h[sIdx] = fmaf(a, h[sIdx], dtx * Bvals[sIdx]);
        }
        S += dt;
    }
    size_t base = (((size_t)rb*NC + c)*DI + d)*DS;
    #pragma unroll
    for (int sIdx = 0; sIdx < DS; sIdx++) {
        g_hend[base + sIdx] = h[sIdx];
        g_pend[base + sIdx] = ex2(A2[sIdx] * S);   // product of a's via cumsum factorization
    }
}

// ---------------- scan pass 2: sequential combine over chunks ----------------
__global__ void scan_combine()
{
    int g = blockIdx.x * 256 + threadIdx.x;  // 2*B*DI*DS = 49152
    if (g >= 2*BB*DI*DS) return;
    int sd = g % (DI*DS);
    int rb = g / (DI*DS);
    float carry = 0.f;
    for (int c = 0; c < NC; c++) {
        size_t idx = ((size_t)rb*NC + c)*(DI*DS) + sd;
        g_hstart[idx] = carry;
        carry = g_pend[idx]*carry + g_hend[idx];
    }
}

// ---------------- scan pass 3: rescan with correct h0, emit y ----------------
__global__ void scan_pass3(const float* __restrict__ A_log)
{
    int d  = blockIdx.x * 128 + threadIdx.x;
    int c  = blockIdx.y;
    int rb = blockIdx.z;
    int r  = rb >> 2, b = rb & 3;

    float A2[DS], h[DS];
    size_t base = (((size_t)rb*NC + c)*DI + d)*DS;
    #pragma unroll
    for (int sIdx = 0; sIdx < DS; sIdx++) {
        A2[sIdx] = -__expf(A_log[d*DS + sIdx]) * LOG2E;
        h[sIdx]  = g_hstart[base + sIdx];
    }
    const float* dtp  = g_dt[r];
    const float* up   = g_xs[r];
    const float* dblp = g_dbl[r];
    float*       yp   = g_y[r];

    for (int t = 0; t < LC; t++) {
        int tau = c*LC + t;
        int pos = r ? (LL - 1 - tau) : tau;
        size_t m = (size_t)b*LL + pos;
        float dt  = dtp[m*DI + d];
        float u   = up [m*DI + d];
        float dtx = dt * u;
        const float4* Bv = (const float4*)(dblp + m*NDBL + DTR);
        const float4* Cv = (const float4*)(dblp + m*NDBL + DTR + DS);
        float4 b0 = Bv[0], b1 = Bv[1], b2 = Bv[2], b3 = Bv[3];
        float4 c0 = Cv[0], c1 = Cv[1], c2 = Cv[2], c3 = Cv[3];
        float Bvals[DS] = {b0.x,b0.y,b0.z,b0.w, b1.x,b1.y,b1.z,b1.w,
                           b2.x,b2.y,b2.z,b2.w, b3.x,b3.y,b3.z,b3.w};
        float Cvals[DS] = {c0.x,c0.y,c0.z,c0.w, c1.x,c1.y,c1.z,c1.w,
                           c2.x,c2.y,c2.z,c2.w, c3.x,c3.y,c3.z,c3.w};
        float y = 0.f;
        #pragma unroll
        for (int sIdx = 0; sIdx < DS; sIdx++) {
            float a = ex2(dt * A2[sIdx]);
            h[sIdx] = fmaf(a, h[sIdx], dtx * Bvals[sIdx]);
            y = fmaf(h[sIdx], Cvals[sIdx], y);
        }
        yp[m*DI + d] = y;
    }
}

// ---------------- fused gate: G = silu(z) * (y_f + y_b + (xs_f+xs_b)*D) ----------------
__global__ void combine_G(const float* __restrict__ Dv)
{
    size_t g = (size_t)blockIdx.x * 256 + threadIdx.x;
    if (g >= (size_t)MM*DI) return;
    int d = (int)(g % DI);
    size_t m = g / DI;
    float z  = g_xz[m*768 + DI + d];
    float sz = silu_f(z);
    float xsum = g_xs[0][g] + g_xs[1][g];
    float ysum = g_y[0][g] + g_y[1][g];
    g_G[g] = sz * (ysum + xsum * Dv[d]);
}

// ---------------- launch ----------------
static float* sym_addr(const void* sym) {
    void* p = nullptr;
    cudaGetSymbolAddress(&p, sym);
    return (float*)p;
}

extern "C" void kernel_launch(void* const* d_in, const int* in_sizes, int n_in,
                              void* d_out, int out_size)
{
    const float* x          = (const float*)d_in[0];
    const float* ln_w       = (const float*)d_in[1];
    const float* ln_b       = (const float*)d_in[2];
    const float* in_proj_w  = (const float*)d_in[3];   // (768, 192)
    const float* conv_w     = (const float*)d_in[4];   // (384, 1, 4)
    const float* conv_b     = (const float*)d_in[5];   // (384,)
    const float* x_proj_w   = (const float*)d_in[6];   // (44, 384)
    const float* dt_proj_w  = (const float*)d_in[7];   // (384, 12)
    const float* dt_proj_b  = (const float*)d_in[8];   // (384,)
    const float* A_log      = (const float*)d_in[9];   // (384, 16)
    const float* D_vec      = (const float*)d_in[10];  // (384,)
    const float* out_proj_w = (const float*)d_in[11];  // (192, 384)
    float* out = (float*)d_out;

    float* p_xn  = sym_addr(g_xn);
    float* p_xz  = sym_addr(g_xz);
    float* p_xs  = sym_addr(g_xs);
    float* p_dbl = sym_addr(g_dbl);
    float* p_dt  = sym_addr(g_dt);
    float* p_G   = sym_addr(g_G);

    // 1) LayerNorm
    ln_kernel<<<dim3(LL/32, BB), dim3(32, 8)>>>(x, ln_w, ln_b);

    // 2) in_proj: xz[M,768] = xn[M,192] @ W^T
    gemm_nt<0><<<dim3(768/64, MM/64), 256>>>(p_xn, in_proj_w, p_xz,
                                             CC, CC, 768, 768, CC, nullptr, nullptr);

    // 3) conv + silu (both directions)
    conv_silu_kernel<<<dim3(LL/16, BB), DI>>>(conv_w, conv_b);

    // 4) x_proj per direction: dbl[M,44] = xs[M,384] @ W^T
    for (int r = 0; r < 2; r++) {
        gemm_nt<0><<<dim3(1, MM/64), 256>>>(p_xs + (size_t)r*MM*DI, x_proj_w,
                                            p_dbl + (size_t)r*MM*NDBL,
                                            DI, DI, NDBL, NDBL, DI, nullptr, nullptr);
    }
    // 5) dt_proj + softplus per direction: dt[M,384] = sp(dbl[:, :12] @ W^T + b)
    for (int r = 0; r < 2; r++) {
        gemm_nt<1><<<dim3(DI/64, MM/64), 256>>>(p_dbl + (size_t)r*MM*NDBL, dt_proj_w,
                                                p_dt + (size_t)r*MM*DI,
                                                NDBL, DTR, DI, DI, DTR, dt_proj_b, nullptr);
    }

    // 6-8) chunked selective scan (both directions in one grid)
    scan_pass1 <<<dim3(DI/128, NC, 2*BB), 128>>>(A_log);
    scan_combine<<<dim3((2*BB*DI*DS + 255)/256), 256>>>();
    scan_pass3 <<<dim3(DI/128, NC, 2*BB), 128>>>(A_log);

    // 9) fused gate
    combine_G<<<dim3((MM*DI + 255)/256), 256>>>(D_vec);

    // 10) out_proj (single GEMM for both directions) with transposed store to (B,C,H,W)
    gemm_nt<2><<<dim3(CC/64, MM/64), 256>>>(p_G, out_proj_w, nullptr,
                                            DI, DI, 0, CC, DI, nullptr, out);
}

// round 2
// speedup vs baseline: 1.4188x; 1.4188x over previous
#include <cuda_runtime.h>
#include <cuda_bf16.h>
#include <math.h>

// ---------------- problem constants ----------------
#define BB   4
#define CC   192
#define HH   64
#define WW   64
#define LL   (HH*WW)          // 4096
#define MM   (BB*LL)          // 16384
#define DI   384
#define DS   16
#define DTR  12
#define NDBL 44               // DTR + 2*DS
#define NC   32               // scan chunks
#define LC   (LL/NC)          // 128
#define LOG2E 1.4426950408889634f

// ---------------- scratch (device globals: allocation-free) ----------------
__device__ float g_xn [MM*CC];
__device__ float g_xz [(size_t)MM*768];
__device__ float g_xs [2][(size_t)MM*DI];
__device__ float g_dbl[2][(size_t)MM*NDBL];
__device__ float g_dt [2][(size_t)MM*DI];
__device__ float g_y  [2][(size_t)MM*DI];
__device__ float g_G  [(size_t)MM*DI];
__device__ float g_hend  [2*BB*NC*DI*DS];
__device__ float g_pend  [2*BB*NC*DI*DS];
__device__ float g_hstart[2*BB*NC*DI*DS];

__device__ __forceinline__ float ex2(float x){
    float r; asm("ex2.approx.ftz.f32 %0, %1;" : "=f"(r) : "f"(x)); return r;
}
__device__ __forceinline__ float silu_f(float x){
    return x / (1.f + __expf(-x));
}

// ---------------- 1) LayerNorm over channels ----------------
__global__ void ln_kernel(const float* __restrict__ x,
                          const float* __restrict__ w,
                          const float* __restrict__ bsh)
{
    int b = blockIdx.y, p0 = blockIdx.x * 32;
    int tx = threadIdx.x, ty = threadIdx.y;
    __shared__ float sx[CC][33];
    __shared__ float red[2][8][32];
    __shared__ float smu[32], srs[32];

    float s1 = 0.f, s2 = 0.f;
    for (int c = ty; c < CC; c += 8) {
        float v = x[((size_t)(b*CC + c))*LL + p0 + tx];
        sx[c][tx] = v; s1 += v; s2 += v*v;
    }
    red[0][ty][tx] = s1; red[1][ty][tx] = s2;
    __syncthreads();
    if (ty == 0) {
        float a = 0.f, q = 0.f;
        #pragma unroll
        for (int j = 0; j < 8; j++){ a += red[0][j][tx]; q += red[1][j][tx]; }
        float mu = a / CC;
        float var = q / CC - mu*mu;
        smu[tx] = mu; srs[tx] = rsqrtf(var + 1e-5f);
    }
    __syncthreads();
    int tid = ty*32 + tx;
    for (int e = tid; e < 32*CC; e += 256) {
        int pp = e / CC, cc = e % CC;
        float v = (sx[cc][pp] - smu[pp]) * srs[pp] * w[cc] + bsh[cc];
        g_xn[((size_t)(b*LL + p0 + pp))*CC + cc] = v;
    }
}

// ---------------- big GEMM: 128x128 tile, TM=TN=8, BK=16 ----------------
// Requires: M%128==0, N%128==0, K%16==0. C[m,n] = sum_k A[m,k]*Bw[n,k]
__global__ __launch_bounds__(256, 2)
void gemm_big(const float* __restrict__ A, const float* __restrict__ Bw,
              float* __restrict__ C, int lda, int ldb, int ldc, int K)
{
    __shared__ __align__(16) float As[16][132];
    __shared__ __align__(16) float Bs[16][132];
    int tid = threadIdx.x;
    int m0 = blockIdx.y * 128, n0 = blockIdx.x * 128;
    int tx = tid % 16, ty = tid / 16;

    float acc[8][8];
    #pragma unroll
    for (int i = 0; i < 8; i++)
        #pragma unroll
        for (int j = 0; j < 8; j++) acc[i][j] = 0.f;

    for (int k0 = 0; k0 < K; k0 += 16) {
        #pragma unroll
        for (int e = 0; e < 2; e++) {
            int idx = tid + e*256;
            int r = idx >> 2, q = idx & 3;
            float4 v = *(const float4*)&A[(size_t)(m0 + r)*lda + k0 + q*4];
            As[q*4+0][r] = v.x; As[q*4+1][r] = v.y;
            As[q*4+2][r] = v.z; As[q*4+3][r] = v.w;
        }
        #pragma unroll
        for (int e = 0; e < 2; e++) {
            int idx = tid + e*256;
            int r = idx >> 2, q = idx & 3;
            float4 v = *(const float4*)&Bw[(size_t)(n0 + r)*ldb + k0 + q*4];
            Bs[q*4+0][r] = v.x; Bs[q*4+1][r] = v.y;
            Bs[q*4+2][r] = v.z; Bs[q*4+3][r] = v.w;
        }
        __syncthreads();
        #pragma unroll
        for (int k = 0; k < 16; k++) {
            float4 a0 = *(const float4*)&As[k][ty*8];
            float4 a1 = *(const float4*)&As[k][ty*8 + 4];
            float4 b0 = *(const float4*)&Bs[k][tx*8];
            float4 b1 = *(const float4*)&Bs[k][tx*8 + 4];
            float a[8] = {a0.x,a0.y,a0.z,a0.w, a1.x,a1.y,a1.z,a1.w};
            float b[8] = {b0.x,b0.y,b0.z,b0.w, b1.x,b1.y,b1.z,b1.w};
            #pragma unroll
            for (int i = 0; i < 8; i++)
                #pragma unroll
                for (int j = 0; j < 8; j++)
                    acc[i][j] = fmaf(a[i], b[j], acc[i][j]);
        }
        __syncthreads();
    }
    #pragma unroll
    for (int i = 0; i < 8; i++) {
        size_t row = (size_t)(m0 + ty*8 + i)*ldc + n0 + tx*8;
        float4 v0 = {acc[i][0], acc[i][1], acc[i][2], acc[i][3]};
        float4 v1 = {acc[i][4], acc[i][5], acc[i][6], acc[i][7]};
        *(float4*)&C[row]     = v0;
        *(float4*)&C[row + 4] = v1;
    }
}

// ---------------- medium GEMM: 128x64 tile, TM=8 TN=4, BK=16 ----------------
// Requires M%128==0. Handles N<=64-per-tile with guards, K arbitrary.
// MODE 0: plain store (with z-batch strides). MODE 1: +bias softplus (z-batch).
// MODE 2: transpose-write to (B,C,L) output layout.
template<int MODE>
__global__ __launch_bounds__(256, 2)
void gemm_med(const float* __restrict__ A, const float* __restrict__ Bw,
              float* __restrict__ C,
              int lda, int ldb, int ldc, int N, int K,
              const float* __restrict__ bias, float* __restrict__ dout,
              size_t aZ, size_t cZ)
{
    __shared__ __align__(16) float As[16][132];
    __shared__ __align__(16) float Bs[16][68];
    __shared__ float strans[(MODE == 2) ? 64*129 : 1];

    A += (size_t)blockIdx.z * aZ;
    C = C ? C + (size_t)blockIdx.z * cZ : C;

    int tid = threadIdx.x;
    int m0 = blockIdx.y * 128, n0 = blockIdx.x * 64;
    int tx = tid % 16, ty = tid / 16;

    float acc[8][4];
    #pragma unroll
    for (int i = 0; i < 8; i++)
        #pragma unroll
        for (int j = 0; j < 4; j++) acc[i][j] = 0.f;

    for (int k0 = 0; k0 < K; k0 += 16) {
        #pragma unroll
        for (int e = 0; e < 2; e++) {
            int idx = tid + e*256;
            int r = idx >> 2, q = idx & 3;
            const float* ap = &A[(size_t)(m0 + r)*lda + k0 + q*4];
            #pragma unroll
            for (int j = 0; j < 4; j++) {
                float v = (k0 + q*4 + j < K) ? ap[j] : 0.f;
                As[q*4+j][r] = v;
            }
        }
        {
            int r = tid >> 2, q = tid & 3;
            bool nok = (n0 + r) < N;
            const float* bp = &Bw[(size_t)(n0 + r)*ldb + k0 + q*4];
            #pragma unroll
            for (int j = 0; j < 4; j++) {
                float v = (nok && (k0 + q*4 + j < K)) ? bp[j] : 0.f;
                Bs[q*4+j][r] = v;
            }
        }
        __syncthreads();
        #pragma unroll
        for (int k = 0; k < 16; k++) {
            float4 a0 = *(const float4*)&As[k][ty*8];
            float4 a1 = *(const float4*)&As[k][ty*8 + 4];
            float4 b0 = *(const float4*)&Bs[k][tx*4];
            float a[8] = {a0.x,a0.y,a0.z,a0.w, a1.x,a1.y,a1.z,a1.w};
            float b[4] = {b0.x,b0.y,b0.z,b0.w};
            #pragma unroll
            for (int i = 0; i < 8; i++)
                #pragma unroll
                for (int j = 0; j < 4; j++)
                    acc[i][j] = fmaf(a[i], b[j], acc[i][j]);
        }
        __syncthreads();
    }

    if (MODE == 0 || MODE == 1) {
        #pragma unroll
        for (int i = 0; i < 8; i++) {
            int m = m0 + ty*8 + i;
            #pragma unroll
            for (int j = 0; j < 4; j++) {
                int n = n0 + tx*4 + j;
                if (n < N) {
                    float v = acc[i][j];
                    if (MODE == 1) {
                        v += bias[n];
                        v = (v > 20.f) ? v : log1pf(expf(v));
                    }
                    C[(size_t)m*ldc + n] = v;
                }
            }
        }
    } else {
        #pragma unroll
        for (int i = 0; i < 8; i++)
            #pragma unroll
            for (int j = 0; j < 4; j++)
                strans[(tx*4 + j)*129 + (ty*8 + i)] = acc[i][j];
        __syncthreads();
        int b = m0 >> 12;
        int p0 = m0 & (LL - 1);
        for (int e = tid; e < 64*128; e += 256) {
            int nn = e >> 7, mm = e & 127;
            int n = n0 + nn;
            if (n < N)
                dout[((size_t)(b*CC + n))*LL + p0 + mm] = strans[nn*129 + mm];
        }
    }
}

// ---------------- depthwise causal conv (both directions) + silu ----------------
__global__ void conv_silu_kernel(const float* __restrict__ cw, const float* __restrict__ cb)
{
    __shared__ float s[16 + 6][DI];
    int b = blockIdx.y, t0 = blockIdx.x * 16, d = threadIdx.x;

    #pragma unroll
    for (int j = 0; j < 22; j++) {
        int t = t0 - 3 + j;
        float v = 0.f;
        if (t >= 0 && t < LL) v = g_xz[((size_t)(b*LL + t))*768 + d];
        s[j][d] = v;
    }
    __syncthreads();
    float w0 = cw[d*4+0], w1 = cw[d*4+1], w2 = cw[d*4+2], w3 = cw[d*4+3];
    float bias = cb[d];
    #pragma unroll
    for (int tt = 0; tt < 16; tt++) {
        float of = w0*s[tt][d] + w1*s[tt+1][d] + w2*s[tt+2][d] + w3*s[tt+3][d] + bias;
        float ob = w3*s[tt+3][d] + w2*s[tt+4][d] + w1*s[tt+5][d] + w0*s[tt+6][d] + bias;
        size_t m = (size_t)(b*LL + t0 + tt);
        g_xs[0][m*DI + d] = silu_f(of);
        g_xs[1][m*DI + d] = silu_f(ob);
    }
}

// ---------------- chunked selective scan ----------------
// PASS3=false: per-chunk local scan -> (h_end, P_end).
// PASS3=true : rescan with h0 from g_hstart, emit y.
// Exploits A_s = -(s+1) structure (runtime-verified) to replace 16 ex2 with
// 1 ex2 + 15 FMUL per timestep; exact-ex2 fallback otherwise.
#define SCAN_LOOP(STRUCTURED, P3)                                              \
    for (int t = 0; t < LC; t++) {                                             \
        int tau = c*LC + t;                                                    \
        int pos = r ? (LL - 1 - tau) : tau;                                    \
        size_t m = (size_t)b*LL + pos;                                         \
        float dt  = dtp[m*DI + d];                                             \
        float u   = up [m*DI + d];                                             \
        float dtx = dt * u;                                                    \
        const float4* Bv = (const float4*)(dblp + m*NDBL + DTR);               \
        float4 b0 = Bv[0], b1 = Bv[1], b2 = Bv[2], b3 = Bv[3];                 \
        float Bvals[DS] = {b0.x,b0.y,b0.z,b0.w, b1.x,b1.y,b1.z,b1.w,           \
                           b2.x,b2.y,b2.z,b2.w, b3.x,b3.y,b3.z,b3.w};          \
        float Cvals[DS];                                                       \
        if (P3) {                                                              \
            const float4* Cv = (const float4*)(dblp + m*NDBL + DTR + DS);      \
            float4 c0 = Cv[0], c1 = Cv[1], c2 = Cv[2], c3 = Cv[3];             \
            Cvals[0]=c0.x; Cvals[1]=c0.y; Cvals[2]=c0.z; Cvals[3]=c0.w;        \
            Cvals[4]=c1.x; Cvals[5]=c1.y; Cvals[6]=c1.z; Cvals[7]=c1.w;        \
            Cvals[8]=c2.x; Cvals[9]=c2.y; Cvals[10]=c2.z; Cvals[11]=c2.w;      \
            Cvals[12]=c3.x;Cvals[13]=c3.y;Cvals[14]=c3.z; Cvals[15]=c3.w;      \
        }                                                                      \
        float e1 = ex2(dt * A2[0]);                                            \
        float a  = e1;                                                         \
        float y  = 0.f;                                                        \
        _Pragma("unroll")                                                      \
        for (int sIdx = 0; sIdx < DS; sIdx++) {                                \
            float av = STRUCTURED ? a : ex2(dt * A2[sIdx]);                    \
            h[sIdx] = fmaf(av, h[sIdx], dtx * Bvals[sIdx]);                    \
            if (P3) y = fmaf(h[sIdx], Cvals[sIdx], y);                         \
            if (STRUCTURED) a *= e1;                                           \
        }                                                                      \
        if (P3) yp[m*DI + d] = y;                                              \
        else    S += dt;                                                       \
    }

template<bool P3>
__global__ void scan_pass(const float* __restrict__ A_log)
{
    int d  = blockIdx.x * 128 + threadIdx.x;
    int c  = blockIdx.y;
    int rb = blockIdx.z;
    int r  = rb >> 2, b = rb & 3;

    float A2[DS], h[DS];
    bool structured = true;
    #pragma unroll
    for (int sIdx = 0; sIdx < DS; sIdx++)
        A2[sIdx] = -__expf(A_log[d*DS + sIdx]) * LOG2E;
    #pragma unroll
    for (int sIdx = 1; sIdx < DS; sIdx++)
        structured &= fabsf(A2[sIdx] - (sIdx+1)*A2[0]) <= 1e-4f*fabsf(A2[sIdx]);

    size_t base = (((size_t)rb*NC + c)*DI + d)*DS;
    #pragma unroll
    for (int sIdx = 0; sIdx < DS; sIdx++)
        h[sIdx] = P3 ? g_hstart[base + sIdx] : 0.f;

    const float* dtp  = g_dt[r];
    const float* up   = g_xs[r];
    const float* dblp = g_dbl[r];
    float*       yp   = g_y[r];
    float S = 0.f;

    if (structured) { SCAN_LOOP(true, P3) }
    else            { SCAN_LOOP(false, P3) }

    if (!P3) {
        #pragma unroll
        for (int sIdx = 0; sIdx < DS; sIdx++) {
            g_hend[base + sIdx] = h[sIdx];
            g_pend[base + sIdx] = ex2(A2[sIdx] * S);
        }
    }
}

// ---------------- scan pass 2: sequential combine over chunks ----------------
__global__ void scan_combine()
{
    int g = blockIdx.x * 256 + threadIdx.x;
    if (g >= 2*BB*DI*DS) return;
    int sd = g % (DI*DS);
    int rb = g / (DI*DS);
    float carry = 0.f;
    for (int c = 0; c < NC; c++) {
        size_t idx = ((size_t)rb*NC + c)*(DI*DS) + sd;
        g_hstart[idx] = carry;
        carry = g_pend[idx]*carry + g_hend[idx];
    }
}

// ---------------- fused gate ----------------
__global__ void combine_G(const float* __restrict__ Dv)
{
    size_t g = (size_t)blockIdx.x * 256 + threadIdx.x;
    if (g >= (size_t)MM*DI) return;
    int d = (int)(g % DI);
    size_t m = g / DI;
    float z  = g_xz[m*768 + DI + d];
    float sz = silu_f(z);
    float xsum = g_xs[0][g] + g_xs[1][g];
    float ysum = g_y[0][g] + g_y[1][g];
    g_G[g] = sz * (ysum + xsum * Dv[d]);
}

// ---------------- launch ----------------
static float* sym_addr(const void* sym) {
    void* p = nullptr;
    cudaGetSymbolAddress(&p, sym);
    return (float*)p;
}

extern "C" void kernel_launch(void* const* d_in, const int* in_sizes, int n_in,
                              void* d_out, int out_size)
{
    const float* x          = (const float*)d_in[0];
    const float* ln_w       = (const float*)d_in[1];
    const float* ln_b       = (const float*)d_in[2];
    const float* in_proj_w  = (const float*)d_in[3];
    const float* conv_w     = (const float*)d_in[4];
    const float* conv_b     = (const float*)d_in[5];
    const float* x_proj_w   = (const float*)d_in[6];
    const float* dt_proj_w  = (const float*)d_in[7];
    const float* dt_proj_b  = (const float*)d_in[8];
    const float* A_log      = (const float*)d_in[9];
    const float* D_vec      = (const float*)d_in[10];
    const float* out_proj_w = (const float*)d_in[11];
    float* out = (float*)d_out;

    float* p_xn  = sym_addr(g_xn);
    float* p_xz  = sym_addr(g_xz);
    float* p_xs  = sym_addr(g_xs);
    float* p_dbl = sym_addr(g_dbl);
    float* p_dt  = sym_addr(g_dt);
    float* p_G   = sym_addr(g_G);

    // 1) LayerNorm
    ln_kernel<<<dim3(LL/32, BB), dim3(32, 8)>>>(x, ln_w, ln_b);

    // 2) in_proj: xz[M,768] = xn[M,192] @ W^T   (128x128 tiles)
    gemm_big<<<dim3(768/128, MM/128), 256>>>(p_xn, in_proj_w, p_xz,
                                             CC, CC, 768, CC);

    // 3) conv + silu (both directions)
    conv_silu_kernel<<<dim3(LL/16, BB), DI>>>(conv_w, conv_b);

    // 4) x_proj both dirs: dbl[M,44] = xs[M,384] @ W^T
    gemm_med<0><<<dim3(1, MM/128, 2), 256>>>(p_xs, x_proj_w, p_dbl,
                                             DI, DI, NDBL, NDBL, DI,
                                             nullptr, nullptr,
                                             (size_t)MM*DI, (size_t)MM*NDBL);

    // 5) dt_proj both dirs: dt[M,384] = softplus(dbl[:, :12] @ W^T + b)
    gemm_med<1><<<dim3(DI/64, MM/128, 2), 256>>>(p_dbl, dt_proj_w, p_dt,
                                                 NDBL, DTR, DI, DI, DTR,
                                                 dt_proj_b, nullptr,
                                                 (size_t)MM*NDBL, (size_t)MM*DI);

    // 6-8) chunked selective scan
    scan_pass<false><<<dim3(DI/128, NC, 2*BB), 128>>>(A_log);
    scan_combine<<<dim3((2*BB*DI*DS + 255)/256), 256>>>();
    scan_pass<true><<<dim3(DI/128, NC, 2*BB), 128>>>(A_log);

    // 9) fused gate
    combine_G<<<dim3((MM*DI + 255)/256), 256>>>(D_vec);

    // 10) out_proj with transposed store to (B,C,H,W)
    gemm_med<2><<<dim3(CC/64, MM/128, 1), 256>>>(p_G, out_proj_w, nullptr,
                                                 DI, DI, 0, CC, DI,
                                                 nullptr, out, 0, 0);
}

// round 5
// speedup vs baseline: 1.9047x; 1.3424x over previous
#include <cuda_runtime.h>
#include <cuda_bf16.h>
#include <cstdint>
#include <math.h>

typedef unsigned int u32;

// ---------------- problem constants ----------------
#define BB   4
#define CC   192
#define HH   64
#define WW   64
#define LL   (HH*WW)          // 4096
#define MM   (BB*LL)          // 16384
#define DI   384
#define DS   16
#define DTR  12
#define NDBL 44               // DTR + 2*DS
#define NC   32               // scan chunks
#define LC   (LL/NC)          // 128
#define LOG2E 1.4426950408889634f

// ---------------- scratch (device globals: allocation-free) ----------------
__device__ __align__(128) float g_xz [(size_t)MM*768];
__device__ __align__(128) float g_xs [2][(size_t)MM*DI];
__device__ __align__(128) float g_dbl[2][(size_t)MM*NDBL];
__device__ __align__(128) float g_dt [2][(size_t)MM*DI];
__device__ __align__(128) float g_y  [2][(size_t)MM*DI];
__device__ float g_hend  [2*BB*NC*DI*DS];
__device__ float g_pend  [2*BB*NC*DI*DS];
__device__ float g_hstart[2*BB*NC*DI*DS];

// bf16 hi/lo pairs for tensor-core GEMMs (k-contiguous natural layouts)
__device__ __align__(128) __nv_bfloat16 g_xnh[(size_t)MM*CC];
__device__ __align__(128) __nv_bfloat16 g_xnl[(size_t)MM*CC];
__device__ __align__(128) __nv_bfloat16 g_xsh[2][(size_t)MM*DI];
__device__ __align__(128) __nv_bfloat16 g_xsl[2][(size_t)MM*DI];
__device__ __align__(128) __nv_bfloat16 g_Gh [(size_t)MM*DI];
__device__ __align__(128) __nv_bfloat16 g_Gl [(size_t)MM*DI];
__device__ __align__(128) __nv_bfloat16 g_wih[768*CC];
__device__ __align__(128) __nv_bfloat16 g_wil[768*CC];
__device__ __align__(128) __nv_bfloat16 g_wxh[128*DI];   // x_proj W padded 44->128 rows
__device__ __align__(128) __nv_bfloat16 g_wxl[128*DI];
__device__ __align__(128) __nv_bfloat16 g_woh[256*DI];   // out_proj W padded 192->256 rows
__device__ __align__(128) __nv_bfloat16 g_wol[256*DI];

__device__ __forceinline__ float ex2(float x){
    float r; asm("ex2.approx.ftz.f32 %0, %1;" : "=f"(r) : "f"(x)); return r;
}
__device__ __forceinline__ float silu_f(float x){
    return x / (1.f + __expf(-x));
}
__device__ __forceinline__ void split_bf16(float v, __nv_bfloat16& h, __nv_bfloat16& l){
    h = __float2bfloat16(v);
    l = __float2bfloat16(v - __bfloat162float(h));
}

// ---------------- PTX helpers ----------------
__device__ __forceinline__ void cpa16(u32 dst, const void* src){
    asm volatile("cp.async.ca.shared.global [%0], [%1], 16;" :: "r"(dst), "l"(src));
}
__device__ __forceinline__ void cp_commit(){
    asm volatile("cp.async.commit_group;");
}
__device__ __forceinline__ void cp_wait1(){
    asm volatile("cp.async.wait_group 1;");
}
__device__ __forceinline__ void cp_wait0(){
    asm volatile("cp.async.wait_group 0;");
}
__device__ __forceinline__ void ldsm4(u32& x0, u32& x1, u32& x2, u32& x3, u32 addr){
    asm volatile("ldmatrix.sync.aligned.m8n8.x4.shared.b16 {%0,%1,%2,%3}, [%4];"
                 : "=r"(x0), "=r"(x1), "=r"(x2), "=r"(x3) : "r"(addr));
}
__device__ __forceinline__ void mma16816(float& d0, float& d1, float& d2, float& d3,
                                         u32 a0, u32 a1, u32 a2, u32 a3,
                                         u32 v0, u32 v1){
    asm volatile("mma.sync.aligned.m16n8k16.row.col.f32.bf16.bf16.f32 "
                 "{%0,%1,%2,%3},{%4,%5,%6,%7},{%8,%9},{%0,%1,%2,%3};"
                 : "+f"(d0), "+f"(d1), "+f"(d2), "+f"(d3)
                 : "r"(a0), "r"(a1), "r"(a2), "r"(a3), "r"(v0), "r"(v1));
}

// ---------------- 1) LayerNorm over channels -> bf16 hi/lo ----------------
__global__ void ln_kernel(const float* __restrict__ x,
                          const float* __restrict__ w,
                          const float* __restrict__ bsh)
{
    int b = blockIdx.y, p0 = blockIdx.x * 32;
    int tx = threadIdx.x, ty = threadIdx.y;
    __shared__ float sx[CC][33];
    __shared__ float red[2][8][32];
    __shared__ float smu[32], srs[32];

    float s1 = 0.f, s2 = 0.f;
    for (int c = ty; c < CC; c += 8) {
        float v = x[((size_t)(b*CC + c))*LL + p0 + tx];
        sx[c][tx] = v; s1 += v; s2 += v*v;
    }
    red[0][ty][tx] = s1; red[1][ty][tx] = s2;
    __syncthreads();
    if (ty == 0) {
        float a = 0.f, q = 0.f;
        #pragma unroll
        for (int j = 0; j < 8; j++){ a += red[0][j][tx]; q += red[1][j][tx]; }
        float mu = a / CC;
        float var = q / CC - mu*mu;
        smu[tx] = mu; srs[tx] = rsqrtf(var + 1e-5f);
    }
    __syncthreads();
    int tid = ty*32 + tx;
    for (int e = tid; e < 32*CC; e += 256) {
        int pp = e / CC, cc = e % CC;
        float v = (sx[cc][pp] - smu[pp]) * srs[pp] * w[cc] + bsh[cc];
        size_t idx = ((size_t)(b*LL + p0 + pp))*CC + cc;
        __nv_bfloat16 h, l; split_bf16(v, h, l);
        g_xnh[idx] = h; g_xnl[idx] = l;
    }
}

// ---------------- weight conversion (hi/lo split + zero padding) ----------------
__global__ void cvt_weights(const float* __restrict__ wi,
                            const float* __restrict__ wx,
                            const float* __restrict__ wo)
{
    int stride = gridDim.x * blockDim.x;
    int t = blockIdx.x * blockDim.x + threadIdx.x;
    for (int e = t; e < 768*CC; e += stride) {
        __nv_bfloat16 h, l; split_bf16(wi[e], h, l);
        g_wih[e] = h; g_wil[e] = l;
    }
    for (int e = t; e < 128*DI; e += stride) {
        int n = e / DI, k = e % DI;
        float v = (n < NDBL) ? wx[n*DI + k] : 0.f;
        __nv_bfloat16 h, l; split_bf16(v, h, l);
        g_wxh[e] = h; g_wxl[e] = l;
    }
    for (int e = t; e < 256*DI; e += stride) {
        int n = e / DI, k = e % DI;
        float v = (n < CC) ? wo[n*DI + k] : 0.f;
        __nv_bfloat16 h, l; split_bf16(v, h, l);
        g_woh[e] = h; g_wol[e] = l;
    }
}

// ---------------- tensor-core GEMM mainloop (shared by both kernels) ----------
// C[m,n] = sum_k A[m,k]*B[n,k], bf16 hi/lo (3 MMAs), fp32 accum.
// BM=BN=128, BK=32, 256 threads (4x2 warps, warp tile 32x64).
#define ROWB   80
#define OFF_AH 0
#define OFF_AL (128*ROWB)
#define OFF_BH (2*128*ROWB)
#define OFF_BL (3*128*ROWB)
#define STAGEB (4*128*ROWB)
#define SMEM_TC (2*STAGEB)

__device__ __forceinline__ void tc_mainloop(
    const __nv_bfloat16* Ahp, const __nv_bfloat16* Alp,
    const __nv_bfloat16* Bhp, const __nv_bfloat16* Blp,
    int K, int m0, int n0, char* smem, float acc[2][8][4])
{
    u32 sbase = (u32)__cvta_generic_to_shared(smem);
    int tid = threadIdx.x;
    int lane = tid & 31, wid = tid >> 5;
    int wm = wid & 3, wn = wid >> 2;

    int r0c = tid >> 2, c0c = tid & 3;
    int r1c = (tid + 256) >> 2, c1c = (tid + 256) & 3;
    int NIT = K / 32;

    for (int pre = 0; pre < 2 && pre < NIT; pre++) {
        int k0 = pre * 32;
        u32 st = sbase + (u32)(pre & 1) * STAGEB;
        cpa16(st + OFF_AH + r0c*ROWB + c0c*16, Ahp + (size_t)(m0 + r0c)*K + k0 + c0c*8);
        cpa16(st + OFF_AH + r1c*ROWB + c1c*16, Ahp + (size_t)(m0 + r1c)*K + k0 + c1c*8);
        cpa16(st + OFF_AL + r0c*ROWB + c0c*16, Alp + (size_t)(m0 + r0c)*K + k0 + c0c*8);
        cpa16(st + OFF_AL + r1c*ROWB + c1c*16, Alp + (size_t)(m0 + r1c)*K + k0 + c1c*8);
        cpa16(st + OFF_BH + r0c*ROWB + c0c*16, Bhp + (size_t)(n0 + r0c)*K + k0 + c0c*8);
        cpa16(st + OFF_BH + r1c*ROWB + c1c*16, Bhp + (size_t)(n0 + r1c)*K + k0 + c1c*8);
        cpa16(st + OFF_BL + r0c*ROWB + c0c*16, Blp + (size_t)(n0 + r0c)*K + k0 + c0c*8);
        cpa16(st + OFF_BL + r1c*ROWB + c1c*16, Blp + (size_t)(n0 + r1c)*K + k0 + c1c*8);
        cp_commit();
    }

    for (int it = 0; it < NIT; it++) {
        cp_wait1();
        __syncthreads();

        u32 st = sbase + (u32)(it & 1) * STAGEB;
        #pragma unroll
        for (int ks = 0; ks < 2; ks++) {
            u32 fah0[4], fah1[4], fal0[4], fal1[4];
            {
                u32 adr0 = st + OFF_AH + (u32)((wm*32 + (lane & 15))*ROWB
                         + ks*32 + (lane >> 4)*16);
                u32 adr1 = adr0 + 16*ROWB;
                ldsm4(fah0[0], fah0[1], fah0[2], fah0[3], adr0);
                ldsm4(fal0[0], fal0[1], fal0[2], fal0[3], adr0 + (OFF_AL - OFF_AH));
                ldsm4(fah1[0], fah1[1], fah1[2], fah1[3], adr1);
                ldsm4(fal1[0], fal1[1], fal1[2], fal1[3], adr1 + (OFF_AL - OFF_AH));
            }
            #pragma unroll
            for (int j = 0; j < 4; j++) {
                u32 fbh[4], fbl[4];
                u32 bdr = st + OFF_BH + (u32)((wn*64 + j*16 + (lane & 15))*ROWB
                        + ks*32 + (lane >> 4)*16);
                ldsm4(fbh[0], fbh[1], fbh[2], fbh[3], bdr);
                ldsm4(fbl[0], fbl[1], fbl[2], fbl[3], bdr + (OFF_BL - OFF_BH));

                mma16816(acc[0][2*j][0], acc[0][2*j][1], acc[0][2*j][2], acc[0][2*j][3],
                         fah0[0], fah0[1], fah0[2], fah0[3], fbh[0], fbh[2]);
                mma16816(acc[0][2*j][0], acc[0][2*j][1], acc[0][2*j][2], acc[0][2*j][3],
                         fah0[0], fah0[1], fah0[2], fah0[3], fbl[0], fbl[2]);
                mma16816(acc[0][2*j][0], acc[0][2*j][1], acc[0][2*j][2], acc[0][2*j][3],
                         fal0[0], fal0[1], fal0[2], fal0[3], fbh[0], fbh[2]);
                mma16816(acc[0][2*j+1][0], acc[0][2*j+1][1], acc[0][2*j+1][2], acc[0][2*j+1][3],
                         fah0[0], fah0[1], fah0[2], fah0[3], fbh[1], fbh[3]);
                mma16816(acc[0][2*j+1][0], acc[0][2*j+1][1], acc[0][2*j+1][2], acc[0][2*j+1][3],
                         fah0[0], fah0[1], fah0[2], fah0[3], fbl[1], fbl[3]);
                mma16816(acc[0][2*j+1][0], acc[0][2*j+1][1], acc[0][2*j+1][2], acc[0][2*j+1][3],
                         fal0[0], fal0[1], fal0[2], fal0[3], fbh[1], fbh[3]);

                mma16816(acc[1][2*j][0], acc[1][2*j][1], acc[1][2*j][2], acc[1][2*j][3],
                         fah1[0], fah1[1], fah1[2], fah1[3], fbh[0], fbh[2]);
                mma16816(acc[1][2*j][0], acc[1][2*j][1], acc[1][2*j][2], acc[1][2*j][3],
                         fah1[0], fah1[1], fah1[2], fah1[3], fbl[0], fbl[2]);
                mma16816(acc[1][2*j][0], acc[1][2*j][1], acc[1][2*j][2], acc[1][2*j][3],
                         fal1[0], fal1[1], fal1[2], fal1[3], fbh[0], fbh[2]);
                mma16816(acc[1][2*j+1][0], acc[1][2*j+1][1], acc[1][2*j+1][2], acc[1][2*j+1][3],
                         fah1[0], fah1[1], fah1[2], fah1[3], fbh[1], fbh[3]);
                mma16816(acc[1][2*j+1][0], acc[1][2*j+1][1], acc[1][2*j+1][2], acc[1][2*j+1][3],
                         fah1[0], fah1[1], fah1[2], fah1[3], fbl[1], fbl[3]);
                mma16816(acc[1][2*j+1][0], acc[1][2*j+1][1], acc[1][2*j+1][2], acc[1][2*j+1][3],
                         fal1[0], fal1[1], fal1[2], fal1[3], fbh[1], fbh[3]);
            }
        }
        __syncthreads();
        if (it + 2 < NIT) {
            int k0 = (it + 2) * 32;
            u32 st2 = sbase + (u32)((it + 2) & 1) * STAGEB;
            cpa16(st2 + OFF_AH + r0c*ROWB + c0c*16, Ahp + (size_t)(m0 + r0c)*K + k0 + c0c*8);
            cpa16(st2 + OFF_AH + r1c*ROWB + c1c*16, Ahp + (size_t)(m0 + r1c)*K + k0 + c1c*8);
            cpa16(st2 + OFF_AL + r0c*ROWB + c0c*16, Alp + (size_t)(m0 + r0c)*K + k0 + c0c*8);
            cpa16(st2 + OFF_AL + r1c*ROWB + c1c*16, Alp + (size_t)(m0 + r1c)*K + k0 + c1c*8);
            cpa16(st2 + OFF_BH + r0c*ROWB + c0c*16, Bhp + (size_t)(n0 + r0c)*K + k0 + c0c*8);
            cpa16(st2 + OFF_BH + r1c*ROWB + c1c*16, Bhp + (size_t)(n0 + r1c)*K + k0 + c1c*8);
            cpa16(st2 + OFF_BL + r0c*ROWB + c0c*16, Blp + (size_t)(n0 + r0c)*K + k0 + c0c*8);
            cpa16(st2 + OFF_BL + r1c*ROWB + c1c*16, Blp + (size_t)(n0 + r1c)*K + k0 + c1c*8);
        }
        cp_commit();
    }
}

// MODE 0: plain fp32 store (z-batched)
__global__ void __launch_bounds__(256)
gemm_tc_store(const __nv_bfloat16* __restrict__ Ahp, const __nv_bfloat16* __restrict__ Alp,
              const __nv_bfloat16* __restrict__ Bhp, const __nv_bfloat16* __restrict__ Blp,
              float* __restrict__ C, int K, int N, int ldc, size_t aZ, size_t cZ)
{
    extern __shared__ char smem[];
    float acc[2][8][4];
    #pragma unroll
    for (int i = 0; i < 2; i++)
        #pragma unroll
        for (int j = 0; j < 8; j++)
            #pragma unroll
            for (int q = 0; q < 4; q++) acc[i][j][q] = 0.f;

    int m0 = blockIdx.y*128, n0 = blockIdx.x*128;
    tc_mainloop(Ahp + (size_t)blockIdx.z*aZ, Alp + (size_t)blockIdx.z*aZ,
                Bhp, Blp, K, m0, n0, smem, acc);
    C += (size_t)blockIdx.z * cZ;

    int lane = threadIdx.x & 31, wid = threadIdx.x >> 5;
    int wm = wid & 3, wn = wid >> 2;
    int gp = lane >> 2, tg = lane & 3;
    #pragma unroll
    for (int mi = 0; mi < 2; mi++) {
        int row = m0 + wm*32 + mi*16 + gp;
        #pragma unroll
        for (int ni = 0; ni < 8; ni++) {
            int col = n0 + wn*64 + ni*8 + tg*2;
            if (col < N) {
                float2 v0; v0.x = acc[mi][ni][0]; v0.y = acc[mi][ni][1];
                float2 v1; v1.x = acc[mi][ni][2]; v1.y = acc[mi][ni][3];
                *(float2*)&C[(size_t)row*ldc + col]       = v0;
                *(float2*)&C[(size_t)(row + 8)*ldc + col] = v1;
            }
        }
    }
}

// MODE 2: transposed store to d_out laid out (B, C, L)
__global__ void __launch_bounds__(256)
gemm_tc_out(const __nv_bfloat16* __restrict__ Ahp, const __nv_bfloat16* __restrict__ Alp,
            const __nv_bfloat16* __restrict__ Bhp, const __nv_bfloat16* __restrict__ Blp,
            int K, int N, float* __restrict__ dout)
{
    extern __shared__ char smem[];
    float acc[2][8][4];
    #pragma unroll
    for (int i = 0; i < 2; i++)
        #pragma unroll
        for (int j = 0; j < 8; j++)
            #pragma unroll
            for (int q = 0; q < 4; q++) acc[i][j][q] = 0.f;

    int m0 = blockIdx.y*128, n0 = blockIdx.x*128;
    tc_mainloop(Ahp, Alp, Bhp, Blp, K, m0, n0, smem, acc);

    cp_wait0();
    __syncthreads();
    float* so = (float*)smem;   // [128][132]
    int lane = threadIdx.x & 31, wid = threadIdx.x >> 5;
    int wm = wid & 3, wn = wid >> 2;
    int gp = lane >> 2, tg = lane & 3;
    #pragma unroll
    for (int mi = 0; mi < 2; mi++) {
        int ml = wm*32 + mi*16 + gp;
        #pragma unroll
        for (int ni = 0; ni < 8; ni++) {
            int nl = wn*64 + ni*8 + tg*2;
            so[(size_t)nl*132 + ml]         = acc[mi][ni][0];
            so[(size_t)(nl+1)*132 + ml]     = acc[mi][ni][1];
            so[(size_t)nl*132 + ml + 8]     = acc[mi][ni][2];
            so[(size_t)(nl+1)*132 + ml + 8] = acc[mi][ni][3];
        }
    }
    __syncthreads();
    int b = m0 >> 12, p0 = m0 & (LL - 1);
    for (int e = threadIdx.x; e < 128*128; e += 256) {
        int nl = e >> 7, mlp = e & 127;
        int n = n0 + nl;
        if (n < N)
            dout[((size_t)(b*CC + n))*LL + p0 + mlp] = so[(size_t)nl*132 + mlp];
    }
}

// ---------------- small GEMM for dt_proj (K=12): 128x64 SIMT ----------------
__global__ void __launch_bounds__(256, 2)
gemm_dt(const float* __restrict__ A, const float* __restrict__ Bw,
        float* __restrict__ C,
        int lda, int ldb, int ldc, int N, int K,
        const float* __restrict__ bias,
        size_t aZ, size_t cZ)
{
    __shared__ __align__(16) float As[16][132];
    __shared__ __align__(16) float Bs[16][68];

    A += (size_t)blockIdx.z * aZ;
    C += (size_t)blockIdx.z * cZ;

    int tid = threadIdx.x;
    int m0 = blockIdx.y * 128, n0 = blockIdx.x * 64;
    int tx = tid % 16, ty = tid / 16;

    float acc[8][4];
    #pragma unroll
    for (int i = 0; i < 8; i++)
        #pragma unroll
        for (int j = 0; j < 4; j++) acc[i][j] = 0.f;

    for (int k0 = 0; k0 < K; k0 += 16) {
        #pragma unroll
        for (int e = 0; e < 2; e++) {
            int idx = tid + e*256;
            int r = idx >> 2, q = idx & 3;
            const float* ap = &A[(size_t)(m0 + r)*lda + k0 + q*4];
            #pragma unroll
            for (int j = 0; j < 4; j++) {
                float v = (k0 + q*4 + j < K) ? ap[j] : 0.f;
                As[q*4+j][r] = v;
            }
        }
        {
            int r = tid >> 2, q = tid & 3;
            bool nok = (n0 + r) < N;
            const float* bp = &Bw[(size_t)(n0 + r)*ldb + k0 + q*4];
            #pragma unroll
            for (int j = 0; j < 4; j++) {
                float v = (nok && (k0 + q*4 + j < K)) ? bp[j] : 0.f;
                Bs[q*4+j][r] = v;
            }
        }
        __syncthreads();
        #pragma unroll
        for (int k = 0; k < 16; k++) {
            float4 a0 = *(const float4*)&As[k][ty*8];
            float4 a1 = *(const float4*)&As[k][ty*8 + 4];
            float4 b0 = *(const float4*)&Bs[k][tx*4];
            float av[8] = {a0.x,a0.y,a0.z,a0.w, a1.x,a1.y,a1.z,a1.w};
            float bv[4] = {b0.x,b0.y,b0.z,b0.w};
            #pragma unroll
            for (int i = 0; i < 8; i++)
                #pragma unroll
                for (int j = 0; j < 4; j++)
                    acc[i][j] = fmaf(av[i], bv[j], acc[i][j]);
        }
        __syncthreads();
    }

    #pragma unroll
    for (int i = 0; i < 8; i++) {
        int m = m0 + ty*8 + i;
        #pragma unroll
        for (int j = 0; j < 4; j++) {
            int n = n0 + tx*4 + j;
            if (n < N) {
                float v = acc[i][j] + bias[n];
                v = (v > 20.f) ? v : log1pf(expf(v));
                C[(size_t)m*ldc + n] = v;
            }
        }
    }
}

// ---------------- depthwise causal conv (both directions) + silu ----------------
__global__ void conv_silu_kernel(const float* __restrict__ cw, const float* __restrict__ cb)
{
    __shared__ float s[16 + 6][DI];
    int b = blockIdx.y, t0 = blockIdx.x * 16, d = threadIdx.x;

    #pragma unroll
    for (int j = 0; j < 22; j++) {
        int t = t0 - 3 + j;
        float v = 0.f;
        if (t >= 0 && t < LL) v = g_xz[((size_t)(b*LL + t))*768 + d];
        s[j][d] = v;
    }
    __syncthreads();
    float w0 = cw[d*4+0], w1 = cw[d*4+1], w2 = cw[d*4+2], w3 = cw[d*4+3];
    float bias = cb[d];
    #pragma unroll
    for (int tt = 0; tt < 16; tt++) {
        float of = w0*s[tt][d] + w1*s[tt+1][d] + w2*s[tt+2][d] + w3*s[tt+3][d] + bias;
        float ob = w3*s[tt+3][d] + w2*s[tt+4][d] + w1*s[tt+5][d] + w0*s[tt+6][d] + bias;
        size_t m = (size_t)(b*LL + t0 + tt);
        float vf = silu_f(of), vb = silu_f(ob);
        g_xs[0][m*DI + d] = vf;
        g_xs[1][m*DI + d] = vb;
        __nv_bfloat16 h, l;
        split_bf16(vf, h, l); g_xsh[0][m*DI + d] = h; g_xsl[0][m*DI + d] = l;
        split_bf16(vb, h, l); g_xsh[1][m*DI + d] = h; g_xsl[1][m*DI + d] = l;
    }
}

// ---------------- chunked selective scan ----------------
#define SCAN_LOOP(STRUCTURED, P3)                                              \
    for (int t = 0; t < LC; t++) {                                             \
        int tau = c*LC + t;                                                    \
        int pos = r ? (LL - 1 - tau) : tau;                                    \
        size_t m = (size_t)b*LL + pos;                                         \
        float dt  = dtp[m*DI + d];                                             \
        float u   = up [m*DI + d];                                             \
        float dtx = dt * u;                                                    \
        const float4* Bv = (const float4*)(dblp + m*NDBL + DTR);               \
        float4 b0 = Bv[0], b1 = Bv[1], b2 = Bv[2], b3 = Bv[3];                 \
        float Bvals[DS] = {b0.x,b0.y,b0.z,b0.w, b1.x,b1.y,b1.z,b1.w,           \
                           b2.x,b2.y,b2.z,b2.w, b3.x,b3.y,b3.z,b3.w};          \
        float Cvals[DS];                                                       \
        if (P3) {                                                              \
            const float4* Cv = (const float4*)(dblp + m*NDBL + DTR + DS);      \
            float4 c0 = Cv[0], c1 = Cv[1], c2 = Cv[2], c3 = Cv[3];             \
            Cvals[0]=c0.x; Cvals[1]=c0.y; Cvals[2]=c0.z; Cvals[3]=c0.w;        \
            Cvals[4]=c1.x; Cvals[5]=c1.y; Cvals[6]=c1.z; Cvals[7]=c1.w;        \
            Cvals[8]=c2.x; Cvals[9]=c2.y; Cvals[10]=c2.z; Cvals[11]=c2.w;      \
            Cvals[12]=c3.x;Cvals[13]=c3.y;Cvals[14]=c3.z; Cvals[15]=c3.w;      \
        }                                                                      \
        float e1 = ex2(dt * A2[0]);                                            \
        float a  = e1;                                                         \
        float y  = 0.f;                                                        \
        _Pragma("unroll")                                                      \
        for (int sIdx = 0; sIdx < DS; sIdx++) {                                \
            float av = STRUCTURED ? a : ex2(dt * A2[sIdx]);                    \
            h[sIdx] = fmaf(av, h[sIdx], dtx * Bvals[sIdx]);                    \
            if (P3) y = fmaf(h[sIdx], Cvals[sIdx], y);                         \
            if (STRUCTURED) a *= e1;                                           \
        }                                                                      \
        if (P3) yp[m*DI + d] = y;                                              \
        else    S += dt;                                                       \
    }

template<bool P3>
__global__ void scan_pass(const float* __restrict__ A_log)
{
    int d  = blockIdx.x * 128 + threadIdx.x;
    int c  = blockIdx.y;
    int rb = blockIdx.z;
    int r  = rb >> 2, b = rb & 3;

    float A2[DS], h[DS];
    bool structured = true;
    #pragma unroll
    for (int sIdx = 0; sIdx < DS; sIdx++)
        A2[sIdx] = -__expf(A_log[d*DS + sIdx]) * LOG2E;
    #pragma unroll
    for (int sIdx = 1; sIdx < DS; sIdx++)
        structured &= fabsf(A2[sIdx] - (sIdx+1)*A2[0]) <= 1e-4f*fabsf(A2[sIdx]);

    size_t base = (((size_t)rb*NC + c)*DI + d)*DS;
    #pragma unroll
    for (int sIdx = 0; sIdx < DS; sIdx++)
        h[sIdx] = P3 ? g_hstart[base + sIdx] : 0.f;

    const float* dtp  = g_dt[r];
    const float* up   = g_xs[r];
    const float* dblp = g_dbl[r];
    float*       yp   = g_y[r];
    float S = 0.f;

    if (structured) { SCAN_LOOP(true, P3) }
    else            { SCAN_LOOP(false, P3) }

    if (!P3) {
        #pragma unroll
        for (int sIdx = 0; sIdx < DS; sIdx++) {
            g_hend[base + sIdx] = h[sIdx];
            g_pend[base + sIdx] = ex2(A2[sIdx] * S);
        }
    }
}

__global__ void scan_combine()
{
    int g = blockIdx.x * 256 + threadIdx.x;
    if (g >= 2*BB*DI*DS) return;
    int sd = g % (DI*DS);
    int rb = g / (DI*DS);
    float carry = 0.f;
    for (int c = 0; c < NC; c++) {
        size_t idx = ((size_t)rb*NC + c)*(DI*DS) + sd;
        g_hstart[idx] = carry;
        carry = g_pend[idx]*carry + g_hend[idx];
    }
}

// ---------------- fused gate -> bf16 hi/lo ----------------
__global__ void combine_G(const float* __restrict__ Dv)
{
    size_t g = (size_t)blockIdx.x * 256 + threadIdx.x;
    if (g >= (size_t)MM*DI) return;
    int d = (int)(g % DI);
    size_t m = g / DI;
    float z  = g_xz[m*768 + DI + d];
    float sz = silu_f(z);
    float xsum = g_xs[0][g] + g_xs[1][g];
    float ysum = g_y[0][g] + g_y[1][g];
    float v = sz * (ysum + xsum * Dv[d]);
    __nv_bfloat16 h, l; split_bf16(v, h, l);
    g_Gh[g] = h; g_Gl[g] = l;
}

// ---------------- launch ----------------
static void* sym_addr(const void* sym) {
    void* p = nullptr;
    cudaGetSymbolAddress(&p, sym);
    return p;
}

extern "C" void kernel_launch(void* const* d_in, const int* in_sizes, int n_in,
                              void* d_out, int out_size)
{
    const float* x          = (const float*)d_in[0];
    const float* ln_w       = (const float*)d_in[1];
    const float* ln_b       = (const float*)d_in[2];
    const float* in_proj_w  = (const float*)d_in[3];
    const float* conv_w     = (const float*)d_in[4];
    const float* conv_b     = (const float*)d_in[5];
    const float* x_proj_w   = (const float*)d_in[6];
    const float* dt_proj_w  = (const float*)d_in[7];
    const float* dt_proj_b  = (const float*)d_in[8];
    const float* A_log      = (const float*)d_in[9];
    const float* D_vec      = (const float*)d_in[10];
    const float* out_proj_w = (const float*)d_in[11];
    float* out = (float*)d_out;

    float* p_xz  = (float*)sym_addr(g_xz);
    float* p_dbl = (float*)sym_addr(g_dbl);
    float* p_dt  = (float*)sym_addr(g_dt);
    __nv_bfloat16* p_xnh = (__nv_bfloat16*)sym_addr(g_xnh);
    __nv_bfloat16* p_xnl = (__nv_bfloat16*)sym_addr(g_xnl);
    __nv_bfloat16* p_xsh = (__nv_bfloat16*)sym_addr(g_xsh);
    __nv_bfloat16* p_xsl = (__nv_bfloat16*)sym_addr(g_xsl);
    __nv_bfloat16* p_Gh  = (__nv_bfloat16*)sym_addr(g_Gh);
    __nv_bfloat16* p_Gl  = (__nv_bfloat16*)sym_addr(g_Gl);
    __nv_bfloat16* p_wih = (__nv_bfloat16*)sym_addr(g_wih);
    __nv_bfloat16* p_wil = (__nv_bfloat16*)sym_addr(g_wil);
    __nv_bfloat16* p_wxh = (__nv_bfloat16*)sym_addr(g_wxh);
    __nv_bfloat16* p_wxl = (__nv_bfloat16*)sym_addr(g_wxl);
    __nv_bfloat16* p_woh = (__nv_bfloat16*)sym_addr(g_woh);
    __nv_bfloat16* p_wol = (__nv_bfloat16*)sym_addr(g_wol);

    cudaFuncSetAttribute((const void*)gemm_tc_store,
                         cudaFuncAttributeMaxDynamicSharedMemorySize, SMEM_TC);
    cudaFuncSetAttribute((const void*)gemm_tc_out,
                         cudaFuncAttributeMaxDynamicSharedMemorySize, SMEM_TC);

    // 1) LayerNorm -> bf16 hi/lo
    ln_kernel<<<dim3(LL/32, BB), dim3(32, 8)>>>(x, ln_w, ln_b);

    // 1b) weight conversion
    cvt_weights<<<256, 256>>>(in_proj_w, x_proj_w, out_proj_w);

    // 2) in_proj: xz[M,768] = xn @ Wi^T  (tensor cores)
    gemm_tc_store<<<dim3(768/128, MM/128, 1), 256, SMEM_TC>>>(
        p_xnh, p_xnl, p_wih, p_wil, p_xz, CC, 768, 768, 0, 0);

    // 3) conv + silu (both directions), emits fp32 + bf16 hi/lo
    conv_silu_kernel<<<dim3(LL/16, BB), DI>>>(conv_w, conv_b);

    // 4) x_proj both dirs: dbl[M,44] = xs @ Wx^T  (tensor cores)
    gemm_tc_store<<<dim3(1, MM/128, 2), 256, SMEM_TC>>>(
        p_xsh, p_xsl, p_wxh, p_wxl, p_dbl, DI, NDBL, NDBL,
        (size_t)MM*DI, (size_t)MM*NDBL);

    // 5) dt_proj both dirs (K=12, SIMT)
    gemm_dt<<<dim3(DI/64, MM/128, 2), 256>>>(
        p_dbl, dt_proj_w, p_dt, NDBL, DTR, DI, DI, DTR, dt_proj_b,
        (size_t)MM*NDBL, (size_t)MM*DI);

    // 6-8) chunked selective scan
    scan_pass<false><<<dim3(DI/128, NC, 2*BB), 128>>>(A_log);
    scan_combine<<<dim3((2*BB*DI*DS + 255)/256), 256>>>();
    scan_pass<true><<<dim3(DI/128, NC, 2*BB), 128>>>(A_log);

    // 9) fused gate -> bf16 hi/lo
    combine_G<<<dim3((MM*DI + 255)/256), 256>>>(D_vec);

    // 10) out_proj (tensor cores) with transposed store to (B,C,H,W)
    gemm_tc_out<<<dim3(2, MM/128, 1), 256, SMEM_TC>>>(
        p_Gh, p_Gl, p_woh, p_wol, DI, CC, out);
}